// round 1
// baseline (speedup 1.0000x reference)
#include <cuda_runtime.h>
#include <cstdio>

// Problem constants (fixed by the reference: B=2,H=16,N=4096,D=64,F=256)
#define BHp   32
#define Np    4096
#define Dp    64
#define Fp    256
#define CHUNK 64
#define GROUPS 16
#define ROWS_PER_GROUP (Np / GROUPS)           // 256
#define CHUNKS_PER_GROUP (ROWS_PER_GROUP / CHUNK) // 4

// Scratch: per-(b,h) kv [F,E] and ksum [F]
__device__ float g_kv[BHp * Fp * Dp];    // 2 MB
__device__ float g_ksum[BHp * Fp];       // 32 KB

__global__ void zero_scratch() {
    int i = blockIdx.x * blockDim.x + threadIdx.x;
    if (i < BHp * Fp * Dp) g_kv[i] = 0.0f;
    if (i < BHp * Fp)      g_ksum[i] = 0.0f;
}

// ---------------------------------------------------------------------------
// Kernel A: k-side. For each (pair, group): compute k' = softmax_kernel(k @ P)
// for 256 rows (4 chunks of 64), accumulate partial kv = k'^T v and ksum in
// registers, then atomically reduce into g_kv / g_ksum.
// smem: Ps[64*256] + xs[64*64] + vs[64*64] + kp[64*256] = 163840 B
// ---------------------------------------------------------------------------
__global__ __launch_bounds__(256, 1)
void kside_kernel(const float* __restrict__ K,
                  const float* __restrict__ V,
                  const float* __restrict__ P) {
    extern __shared__ float sm[];
    float* Ps = sm;                    // [64][256] projection matrix
    float* xs = Ps + Dp * Fp;          // [64][64]  k tile
    float* vs = xs + CHUNK * Dp;       // [64][64]  v tile
    float* kp = vs + CHUNK * Dp;       // [64][256] k' tile

    const int tid  = threadIdx.x;
    const int w    = tid >> 5;         // warp 0..7
    const int lane = tid & 31;
    const int pair = blockIdx.y;       // 0..31
    const int grp  = blockIdx.x;       // 0..15

    // load P (coalesced float4)
    for (int i = tid; i < Dp * Fp / 4; i += 256)
        ((float4*)Ps)[i] = ((const float4*)P)[i];

    // persistent accumulators: kv micro-tile acc[f=lane+32i][e=w*8+j], ksum part
    float acc[8][8];
    #pragma unroll
    for (int i = 0; i < 8; i++)
        #pragma unroll
        for (int j = 0; j < 8; j++) acc[i][j] = 0.0f;
    float ksp[8];
    #pragma unroll
    for (int j = 0; j < 8; j++) ksp[j] = 0.0f;

    __syncthreads();

    for (int c = 0; c < CHUNKS_PER_GROUP; c++) {
        const int row0 = grp * ROWS_PER_GROUP + c * CHUNK;
        const float* ksrc = K + ((size_t)pair * Np + row0) * Dp;
        const float* vsrc = V + ((size_t)pair * Np + row0) * Dp;
        for (int i = tid; i < CHUNK * Dp / 4; i += 256) {
            ((float4*)xs)[i] = ((const float4*)ksrc)[i];
            ((float4*)vs)[i] = ((const float4*)vsrc)[i];
        }
        __syncthreads();

        // ---- phase 1: projection. warp w owns rows w*8..w*8+7,
        //      lane owns features lane+32*j (j=0..7)
        float pr[8][8];
        #pragma unroll
        for (int i = 0; i < 8; i++)
            #pragma unroll
            for (int j = 0; j < 8; j++) pr[i][j] = 0.0f;

        for (int d = 0; d < Dp; d += 4) {
            float4 a4[8];
            #pragma unroll
            for (int i = 0; i < 8; i++)
                a4[i] = *(const float4*)&xs[(w * 8 + i) * Dp + d];
            #pragma unroll
            for (int dd = 0; dd < 4; dd++) {
                float bb[8];
                #pragma unroll
                for (int j = 0; j < 8; j++)
                    bb[j] = Ps[(d + dd) * Fp + lane + 32 * j];
                #pragma unroll
                for (int i = 0; i < 8; i++) {
                    const float av = (&a4[i].x)[dd];
                    #pragma unroll
                    for (int j = 0; j < 8; j++)
                        pr[i][j] = fmaf(av, bb[j], pr[i][j]);
                }
            }
        }

        // ---- softmax-kernel: row max (warp reduce), exp, scale 1/sqrt(256)
        #pragma unroll
        for (int i = 0; i < 8; i++) {
            float m = pr[i][0];
            #pragma unroll
            for (int j = 1; j < 8; j++) m = fmaxf(m, pr[i][j]);
            #pragma unroll
            for (int off = 16; off > 0; off >>= 1)
                m = fmaxf(m, __shfl_xor_sync(0xffffffffu, m, off));
            #pragma unroll
            for (int j = 0; j < 8; j++) {
                const float e = expf(pr[i][j] - m) * 0.0625f;
                kp[(w * 8 + i) * Fp + lane + 32 * j] = e;
                ksp[j] += e;
            }
        }
        __syncthreads();

        // ---- phase 2: kv += k'^T v over this chunk's 64 rows
        //      thread owns f = lane+32*i, e = w*8+j
        for (int r = 0; r < CHUNK; r++) {
            float a_[8];
            #pragma unroll
            for (int i = 0; i < 8; i++)
                a_[i] = kp[r * Fp + lane + 32 * i];
            const float4 b0 = *(const float4*)&vs[r * Dp + w * 8];
            const float4 b1 = *(const float4*)&vs[r * Dp + w * 8 + 4];
            const float b_[8] = {b0.x, b0.y, b0.z, b0.w, b1.x, b1.y, b1.z, b1.w};
            #pragma unroll
            for (int i = 0; i < 8; i++)
                #pragma unroll
                for (int j = 0; j < 8; j++)
                    acc[i][j] = fmaf(a_[i], b_[j], acc[i][j]);
        }
        __syncthreads();
    }

    // ---- reduce into global scratch
    float* kvg = g_kv + (size_t)pair * Fp * Dp;
    #pragma unroll
    for (int i = 0; i < 8; i++)
        #pragma unroll
        for (int j = 0; j < 8; j++)
            atomicAdd(&kvg[(lane + 32 * i) * Dp + w * 8 + j], acc[i][j]);
    float* ksg = g_ksum + (size_t)pair * Fp;
    #pragma unroll
    for (int j = 0; j < 8; j++)
        atomicAdd(&ksg[lane + 32 * j], ksp[j]);
}

// ---------------------------------------------------------------------------
// Kernel B: q-side. q' projection, then out = (q' kv) / (q' (ksum+1e-6)).
// smem: Ps[64*256] + xs[64*64] + qp[64*256] + kvs[256*64] + kss[256] = 214016 B
// ---------------------------------------------------------------------------
__global__ __launch_bounds__(256, 1)
void qside_kernel(const float* __restrict__ Q,
                  const float* __restrict__ P,
                  float* __restrict__ out) {
    extern __shared__ float sm[];
    float* Ps  = sm;                    // [64][256]
    float* xs  = Ps + Dp * Fp;          // [64][64]
    float* qp  = xs + CHUNK * Dp;       // [64][256]
    float* kvs = qp + CHUNK * Fp;       // [256][64]
    float* kss = kvs + Fp * Dp;         // [256]

    const int tid  = threadIdx.x;
    const int w    = tid >> 5;
    const int lane = tid & 31;
    const int pair = blockIdx.y;
    const int grp  = blockIdx.x;

    for (int i = tid; i < Dp * Fp / 4; i += 256)
        ((float4*)Ps)[i] = ((const float4*)P)[i];
    {
        const float* kvg = g_kv + (size_t)pair * Fp * Dp;
        for (int i = tid; i < Fp * Dp / 4; i += 256)
            ((float4*)kvs)[i] = ((const float4*)kvg)[i];
        kss[tid] = g_ksum[(size_t)pair * Fp + tid] + 1e-6f;
    }
    __syncthreads();

    for (int c = 0; c < CHUNKS_PER_GROUP; c++) {
        const int row0 = grp * ROWS_PER_GROUP + c * CHUNK;
        const float* qsrc = Q + ((size_t)pair * Np + row0) * Dp;
        for (int i = tid; i < CHUNK * Dp / 4; i += 256)
            ((float4*)xs)[i] = ((const float4*)qsrc)[i];
        __syncthreads();

        // ---- phase 1: projection (identical structure to kside)
        float pr[8][8];
        #pragma unroll
        for (int i = 0; i < 8; i++)
            #pragma unroll
            for (int j = 0; j < 8; j++) pr[i][j] = 0.0f;

        for (int d = 0; d < Dp; d += 4) {
            float4 a4[8];
            #pragma unroll
            for (int i = 0; i < 8; i++)
                a4[i] = *(const float4*)&xs[(w * 8 + i) * Dp + d];
            #pragma unroll
            for (int dd = 0; dd < 4; dd++) {
                float bb[8];
                #pragma unroll
                for (int j = 0; j < 8; j++)
                    bb[j] = Ps[(d + dd) * Fp + lane + 32 * j];
                #pragma unroll
                for (int i = 0; i < 8; i++) {
                    const float av = (&a4[i].x)[dd];
                    #pragma unroll
                    for (int j = 0; j < 8; j++)
                        pr[i][j] = fmaf(av, bb[j], pr[i][j]);
                }
            }
        }
        #pragma unroll
        for (int i = 0; i < 8; i++) {
            float m = pr[i][0];
            #pragma unroll
            for (int j = 1; j < 8; j++) m = fmaxf(m, pr[i][j]);
            #pragma unroll
            for (int off = 16; off > 0; off >>= 1)
                m = fmaxf(m, __shfl_xor_sync(0xffffffffu, m, off));
            #pragma unroll
            for (int j = 0; j < 8; j++)
                qp[(w * 8 + i) * Fp + lane + 32 * j] = expf(pr[i][j] - m) * 0.0625f;
        }
        __syncthreads();

        // ---- phase 2: out rows w*8+i, cols lane*2 .. lane*2+1; denom per row
        float oacc[8][2];
        float dn[8];
        #pragma unroll
        for (int i = 0; i < 8; i++) { oacc[i][0] = 0.0f; oacc[i][1] = 0.0f; dn[i] = 0.0f; }

        for (int f = 0; f < Fp; f++) {
            float a_[8];
            #pragma unroll
            for (int i = 0; i < 8; i++)
                a_[i] = qp[(w * 8 + i) * Fp + f];          // warp-uniform broadcast
            const float2 b = *(const float2*)&kvs[f * Dp + lane * 2];
            const float ks = kss[f];
            #pragma unroll
            for (int i = 0; i < 8; i++) {
                oacc[i][0] = fmaf(a_[i], b.x, oacc[i][0]);
                oacc[i][1] = fmaf(a_[i], b.y, oacc[i][1]);
                dn[i]      = fmaf(a_[i], ks,  dn[i]);
            }
        }

        float* od = out + ((size_t)pair * Np + row0) * Dp;
        #pragma unroll
        for (int i = 0; i < 8; i++) {
            const float inv = 1.0f / dn[i];
            float2 o;
            o.x = oacc[i][0] * inv;
            o.y = oacc[i][1] * inv;
            *(float2*)&od[(w * 8 + i) * Dp + lane * 2] = o;
        }
        __syncthreads();
    }
}

// ---------------------------------------------------------------------------
extern "C" void kernel_launch(void* const* d_in, const int* in_sizes, int n_in,
                              void* d_out, int out_size) {
    const float* q = (const float*)d_in[0];
    const float* k = (const float*)d_in[1];
    const float* v = (const float*)d_in[2];
    const float* p = (const float*)d_in[3];
    float* out = (float*)d_out;

    static_assert(sizeof(float4) == 16, "");

    const size_t smemA = (size_t)(Dp * Fp + CHUNK * Dp + CHUNK * Dp + CHUNK * Fp) * 4;           // 163840
    const size_t smemB = (size_t)(Dp * Fp + CHUNK * Dp + CHUNK * Fp + Fp * Dp + Fp) * 4;         // 214016

    cudaFuncSetAttribute(kside_kernel, cudaFuncAttributeMaxDynamicSharedMemorySize, (int)smemA);
    cudaFuncSetAttribute(qside_kernel, cudaFuncAttributeMaxDynamicSharedMemorySize, (int)smemB);

    // zero kv/ksum scratch (must happen every replay)
    {
        int total = BHp * Fp * Dp;   // covers ksum too (smaller)
        int blocks = (total + 255) / 256;
        zero_scratch<<<blocks, 256>>>();
    }

    dim3 grid(GROUPS, BHp);
    kside_kernel<<<grid, 256, smemA>>>(k, v, p);
    qside_kernel<<<grid, 256, smemB>>>(q, p, out);
}